// round 14
// baseline (speedup 1.0000x reference)
#include <cuda_runtime.h>

#define SS   224
#define PP   30
#define CROPV 164
#define BB   16
#define TT   16
#define TG   4                             // frames per thread
#define NTG  (TT / TG)                     // 4 t-groups
#define J4   (SS / 4)                      // 56 float4 per row
#define TOTAL_THREADS (BB * 3 * SS * J4 * NTG)   // 2408448 = 18816 * 128

__global__ __launch_bounds__(128) void prompter_add_kernel(
    const float* __restrict__ x,        // [B,3,T,S,S]
    const float* __restrict__ pu,       // [3,3,2P,S]
    const float* __restrict__ pd,       // [3,3,P,S]
    const float* __restrict__ pl,       // [3,3,CROP,2P]
    const float* __restrict__ pr,       // [3,3,CROP,P]
    const int*   __restrict__ cams,     // [B]
    const int*   __restrict__ offs_r,   // [B]
    const int*   __restrict__ offs_d,   // [B]
    float* __restrict__ out)            // [B,3,T,S,S]
{
    int tid = blockIdx.x * blockDim.x + threadIdx.x;

    int j4 = tid % J4;
    int i  = (tid / J4) % SS;
    int c  = (tid / (J4 * SS)) % 3;
    int b  = (tid / (J4 * SS * 3)) % BB;
    int tg =  tid / (J4 * SS * 3 * BB);
    int j  = j4 * 4;

    // ---- issue the 4 frame loads FIRST (front-batched; MLP_p1 = 4).
    size_t base = ((((size_t)b * 3 + c) * TT) + (size_t)tg * TG) * (size_t)(SS * SS)
                + (size_t)i * SS + (size_t)j;
    const float4* xin  = (const float4*)(x + base);
    float4*       oout = (float4*)(out + base);
    const int stride4 = (SS * SS) / 4;   // float4 stride between frames

    float4 xv0 = __ldg(xin);
    float4 xv1 = __ldg(xin + stride4);
    float4 xv2 = __ldg(xin + 2 * stride4);
    float4 xv3 = __ldg(xin + 3 * stride4);

    // ---- compute prompt value (overlapped with the loads above)
    int cam = cams[b];
    int orr = offs_r[b];
    int od  = offs_d[b];
    int off_l = 2 * PP - orr;   // [30,59]
    int off_u = 2 * PP - od;    // [30,59]

    float4 pv;

    if (i < off_u) {
        // top band: vertical interp between two rows of pad_up (in_size=60)
        float scale = 60.0f / (float)off_u;
        float f = fmaxf(((float)i + 0.5f) * scale - 0.5f, 0.0f);
        int   r0 = (int)floorf(f);
        float w  = f - (float)r0;
        int   r1 = min(r0 + 1, 59);
        const float4* row0 = (const float4*)(pu + ((size_t)(cam * 3 + c) * 60 + r0) * SS) + j4;
        const float4* row1 = (const float4*)(pu + ((size_t)(cam * 3 + c) * 60 + r1) * SS) + j4;
        float4 a = __ldg(row0);
        float4 d = __ldg(row1);
        float om = 1.0f - w;
        pv.x = a.x * om + d.x * w;
        pv.y = a.y * om + d.y * w;
        pv.z = a.z * om + d.z * w;
        pv.w = a.w * om + d.w * w;
    } else if (i >= SS - od) {
        // bottom band: vertical interp between two rows of pad_down (in_size=30)
        float scale = 30.0f / (float)od;
        float pos = (float)(i - (SS - od));
        float f = fmaxf((pos + 0.5f) * scale - 0.5f, 0.0f);
        int   r0 = (int)floorf(f);
        float w  = f - (float)r0;
        int   r1 = min(r0 + 1, 29);
        const float4* row0 = (const float4*)(pd + ((size_t)(cam * 3 + c) * 30 + r0) * SS) + j4;
        const float4* row1 = (const float4*)(pd + ((size_t)(cam * 3 + c) * 30 + r1) * SS) + j4;
        float4 a = __ldg(row0);
        float4 d = __ldg(row1);
        float om = 1.0f - w;
        pv.x = a.x * om + d.x * w;
        pv.y = a.y * om + d.y * w;
        pv.z = a.z * om + d.z * w;
        pv.w = a.w * om + d.w * w;
    } else {
        // middle band: horizontal interp (left pad / zero / right pad), row r
        int r = i - off_u;                 // [0, CROP)
        const float* lrow = pl + ((size_t)(cam * 3 + c) * CROPV + r) * (2 * PP);
        const float* rrow = pr + ((size_t)(cam * 3 + c) * CROPV + r) * PP;
        float vals[4];
        #pragma unroll
        for (int k = 0; k < 4; k++) {
            int jj = j + k;
            float v = 0.0f;
            if (jj < off_l) {
                float scale = 60.0f / (float)off_l;
                float f = fmaxf(((float)jj + 0.5f) * scale - 0.5f, 0.0f);
                int   c0 = (int)floorf(f);
                float w  = f - (float)c0;
                int   c1 = min(c0 + 1, 59);
                v = __ldg(lrow + c0) * (1.0f - w) + __ldg(lrow + c1) * w;
            } else if (jj >= SS - orr) {
                float scale = 30.0f / (float)orr;
                float pos = (float)(jj - (SS - orr));
                float f = fmaxf((pos + 0.5f) * scale - 0.5f, 0.0f);
                int   c0 = (int)floorf(f);
                float w  = f - (float)c0;
                int   c1 = min(c0 + 1, 29);
                v = __ldg(rrow + c0) * (1.0f - w) + __ldg(rrow + c1) * w;
            }
            vals[k] = v;
        }
        pv.x = vals[0]; pv.y = vals[1]; pv.z = vals[2]; pv.w = vals[3];
    }

    // ---- add & store
    xv0.x += pv.x; xv0.y += pv.y; xv0.z += pv.z; xv0.w += pv.w;
    xv1.x += pv.x; xv1.y += pv.y; xv1.z += pv.z; xv1.w += pv.w;
    xv2.x += pv.x; xv2.y += pv.y; xv2.z += pv.z; xv2.w += pv.w;
    xv3.x += pv.x; xv3.y += pv.y; xv3.z += pv.z; xv3.w += pv.w;
    oout[0]           = xv0;
    oout[stride4]     = xv1;
    oout[2 * stride4] = xv2;
    oout[3 * stride4] = xv3;
}

extern "C" void kernel_launch(void* const* d_in, const int* in_sizes, int n_in,
                              void* d_out, int out_size) {
    const float* x   = (const float*)d_in[0];
    const float* pu  = (const float*)d_in[1];
    const float* pd  = (const float*)d_in[2];
    const float* pl  = (const float*)d_in[3];
    const float* pr  = (const float*)d_in[4];
    const int*   cam = (const int*)d_in[5];
    const int*   orr = (const int*)d_in[6];
    const int*   od  = (const int*)d_in[7];
    float* out = (float*)d_out;

    const int threads = 128;
    const int blocks  = TOTAL_THREADS / threads;  // 18816
    prompter_add_kernel<<<blocks, threads>>>(x, pu, pd, pl, pr, cam, orr, od, out);
}

// round 15
// speedup vs baseline: 1.0574x; 1.0574x over previous
#include <cuda_runtime.h>

#define SS   224
#define PP   30
#define CROPV 164
#define BB   16
#define TT   16
#define TG   4                             // frames per thread
#define NTG  (TT / TG)                     // 4 t-groups
#define J4   (SS / 4)                      // 56 float4 per row
#define TOTAL_THREADS (BB * 3 * SS * J4 * NTG)   // 2408448 = 9408 * 256

__global__ __launch_bounds__(256) void prompter_add_kernel(
    const float* __restrict__ x,        // [B,3,T,S,S]
    const float* __restrict__ pu,       // [3,3,2P,S]
    const float* __restrict__ pd,       // [3,3,P,S]
    const float* __restrict__ pl,       // [3,3,CROP,2P]
    const float* __restrict__ pr,       // [3,3,CROP,P]
    const int*   __restrict__ cams,     // [B]
    const int*   __restrict__ offs_r,   // [B]
    const int*   __restrict__ offs_d,   // [B]
    float* __restrict__ out)            // [B,3,T,S,S]
{
    int tid = blockIdx.x * blockDim.x + threadIdx.x;

    int j4 = tid % J4;
    int i  = (tid / J4) % SS;
    int c  = (tid / (J4 * SS)) % 3;
    int b  = (tid / (J4 * SS * 3)) % BB;
    int tg =  tid / (J4 * SS * 3 * BB);
    int j  = j4 * 4;

    // ---- issue the 4 frame loads FIRST (front-batched; MLP_p1 = 4).
    // Their addresses depend only on tid, so they overlap the entire
    // prompt-interp computation below.
    size_t base = ((((size_t)b * 3 + c) * TT) + (size_t)tg * TG) * (size_t)(SS * SS)
                + (size_t)i * SS + (size_t)j;
    const float4* xin  = (const float4*)(x + base);
    float4*       oout = (float4*)(out + base);
    const int stride4 = (SS * SS) / 4;   // float4 stride between frames

    float4 xv0 = __ldg(xin);
    float4 xv1 = __ldg(xin + stride4);
    float4 xv2 = __ldg(xin + 2 * stride4);
    float4 xv3 = __ldg(xin + 3 * stride4);

    // ---- compute prompt value (overlapped with the loads above)
    int cam = cams[b];
    int orr = offs_r[b];
    int od  = offs_d[b];
    int off_l = 2 * PP - orr;   // [30,59]
    int off_u = 2 * PP - od;    // [30,59]

    float4 pv;

    if (i < off_u) {
        // top band: vertical interp between two rows of pad_up (in_size=60)
        float scale = 60.0f / (float)off_u;
        float f = fmaxf(((float)i + 0.5f) * scale - 0.5f, 0.0f);
        int   r0 = (int)floorf(f);
        float w  = f - (float)r0;
        int   r1 = min(r0 + 1, 59);
        const float4* row0 = (const float4*)(pu + ((size_t)(cam * 3 + c) * 60 + r0) * SS) + j4;
        const float4* row1 = (const float4*)(pu + ((size_t)(cam * 3 + c) * 60 + r1) * SS) + j4;
        float4 a = __ldg(row0);
        float4 d = __ldg(row1);
        float om = 1.0f - w;
        pv.x = a.x * om + d.x * w;
        pv.y = a.y * om + d.y * w;
        pv.z = a.z * om + d.z * w;
        pv.w = a.w * om + d.w * w;
    } else if (i >= SS - od) {
        // bottom band: vertical interp between two rows of pad_down (in_size=30)
        float scale = 30.0f / (float)od;
        float pos = (float)(i - (SS - od));
        float f = fmaxf((pos + 0.5f) * scale - 0.5f, 0.0f);
        int   r0 = (int)floorf(f);
        float w  = f - (float)r0;
        int   r1 = min(r0 + 1, 29);
        const float4* row0 = (const float4*)(pd + ((size_t)(cam * 3 + c) * 30 + r0) * SS) + j4;
        const float4* row1 = (const float4*)(pd + ((size_t)(cam * 3 + c) * 30 + r1) * SS) + j4;
        float4 a = __ldg(row0);
        float4 d = __ldg(row1);
        float om = 1.0f - w;
        pv.x = a.x * om + d.x * w;
        pv.y = a.y * om + d.y * w;
        pv.z = a.z * om + d.z * w;
        pv.w = a.w * om + d.w * w;
    } else {
        // middle band: horizontal interp (left pad / zero / right pad), row r
        int r = i - off_u;                 // [0, CROP)
        const float* lrow = pl + ((size_t)(cam * 3 + c) * CROPV + r) * (2 * PP);
        const float* rrow = pr + ((size_t)(cam * 3 + c) * CROPV + r) * PP;
        float vals[4];
        #pragma unroll
        for (int k = 0; k < 4; k++) {
            int jj = j + k;
            float v = 0.0f;
            if (jj < off_l) {
                float scale = 60.0f / (float)off_l;
                float f = fmaxf(((float)jj + 0.5f) * scale - 0.5f, 0.0f);
                int   c0 = (int)floorf(f);
                float w  = f - (float)c0;
                int   c1 = min(c0 + 1, 59);
                v = __ldg(lrow + c0) * (1.0f - w) + __ldg(lrow + c1) * w;
            } else if (jj >= SS - orr) {
                float scale = 30.0f / (float)orr;
                float pos = (float)(jj - (SS - orr));
                float f = fmaxf((pos + 0.5f) * scale - 0.5f, 0.0f);
                int   c0 = (int)floorf(f);
                float w  = f - (float)c0;
                int   c1 = min(c0 + 1, 29);
                v = __ldg(rrow + c0) * (1.0f - w) + __ldg(rrow + c1) * w;
            }
            vals[k] = v;
        }
        pv.x = vals[0]; pv.y = vals[1]; pv.z = vals[2]; pv.w = vals[3];
    }

    // ---- add & store
    xv0.x += pv.x; xv0.y += pv.y; xv0.z += pv.z; xv0.w += pv.w;
    xv1.x += pv.x; xv1.y += pv.y; xv1.z += pv.z; xv1.w += pv.w;
    xv2.x += pv.x; xv2.y += pv.y; xv2.z += pv.z; xv2.w += pv.w;
    xv3.x += pv.x; xv3.y += pv.y; xv3.z += pv.z; xv3.w += pv.w;
    oout[0]           = xv0;
    oout[stride4]     = xv1;
    oout[2 * stride4] = xv2;
    oout[3 * stride4] = xv3;
}

extern "C" void kernel_launch(void* const* d_in, const int* in_sizes, int n_in,
                              void* d_out, int out_size) {
    const float* x   = (const float*)d_in[0];
    const float* pu  = (const float*)d_in[1];
    const float* pd  = (const float*)d_in[2];
    const float* pl  = (const float*)d_in[3];
    const float* pr  = (const float*)d_in[4];
    const int*   cam = (const int*)d_in[5];
    const int*   orr = (const int*)d_in[6];
    const int*   od  = (const int*)d_in[7];
    float* out = (float*)d_out;

    const int threads = 256;
    const int blocks  = TOTAL_THREADS / threads;  // 9408
    prompter_add_kernel<<<blocks, threads>>>(x, pu, pd, pl, pr, cam, orr, od, out);
}